// round 1
// baseline (speedup 1.0000x reference)
#include <cuda_runtime.h>

#define NROWS 8192
#define DDIM  128
#define BM    128
#define BN    128
#define SPLITS 2
#define LDSM  132          // padded smem row stride (floats)
#define MARGIN 0.3f

// -------- device scratch (no allocations allowed) --------
__device__ int      g_mode64;
__device__ int      g_lab[NROWS];
__device__ float    g_sqnorm[NROWS];
__device__ unsigned g_hp[NROWS];   // squared hardest-positive, float bits (>=0 -> uint order == float order)
__device__ unsigned g_hn[NROWS];   // squared hardest-negative, float bits

// -------- labels: detect int64 vs int32 encoding --------
// If labels are int64 (values 0..255), every odd int32 word of the buffer is 0.
// Checks only the first 4096 int32 words (16 KB) -> in-bounds for either dtype.
__global__ void detect_kernel(const int* __restrict__ lab32) {
    __shared__ unsigned red[8];
    unsigned o = 0;
    for (int i = threadIdx.x; i < 2048; i += 256)
        o |= (unsigned)lab32[2 * i + 1];
    #pragma unroll
    for (int s = 16; s; s >>= 1) o |= __shfl_xor_sync(0xffffffffu, o, s);
    if ((threadIdx.x & 31) == 0) red[threadIdx.x >> 5] = o;
    __syncthreads();
    if (threadIdx.x == 0) {
        unsigned t = 0;
        #pragma unroll
        for (int i = 0; i < 8; i++) t |= red[i];
        g_mode64 = (t == 0) ? 1 : 0;
    }
}

__global__ void convert_kernel(const int* __restrict__ lab32) {
    int i = blockIdx.x * blockDim.x + threadIdx.x;
    if (i < NROWS) {
        int m = g_mode64;
        g_lab[i] = m ? lab32[2 * i] : lab32[i];
    }
}

// -------- squared norms + init of the mining scratch --------
__global__ void norms_kernel(const float* __restrict__ X) {
    int w = threadIdx.x >> 5, lane = threadIdx.x & 31;
    int row = blockIdx.x * 8 + w;
    const float* xr = X + row * DDIM;
    float s = 0.f;
    #pragma unroll
    for (int k = lane; k < DDIM; k += 32) { float v = xr[k]; s = fmaf(v, v, s); }
    #pragma unroll
    for (int o = 16; o; o >>= 1) s += __shfl_xor_sync(0xffffffffu, s, o);
    if (lane == 0) {
        g_sqnorm[row] = s;
        g_hp[row] = 0u;                 // max over non-negative starts at 0 (matches where(same,d,0))
        g_hn[row] = 0x7f800000u;        // +inf
    }
}

// -------- fused Gram-tile + hard-pos/neg mining --------
// grid: (64 row tiles, SPLITS column splits), 256 threads, 8x8 register tile.
__global__ __launch_bounds__(256, 1)
void tile_kernel(const float* __restrict__ X) {
    extern __shared__ float smem[];
    float* As    = smem;                    // [DDIM][LDSM] k-major
    float* Bs    = smem + DDIM * LDSM;      // [DDIM][LDSM] k-major
    float* s_sqb = Bs + DDIM * LDSM;        // [BN]
    int*   s_lab = (int*)(s_sqb + BN);      // [BN]

    const int tid = threadIdx.x;
    const int tx = tid & 15, ty = tid >> 4;
    const int row0 = blockIdx.x * BM;

    // Load+transpose A tile once (K=128 fits entirely).
    // idx -> (m = idx&127, kq = idx>>7): warp covers 32 rows at one 16B column
    // (scattered 32B-sector global reads from L2-resident X; conflict-free STS).
    for (int idx = tid; idx < BM * (DDIM / 4); idx += 256) {
        int m = idx & (BM - 1), kq = idx >> 7;
        float4 v = *reinterpret_cast<const float4*>(X + (row0 + m) * DDIM + kq * 4);
        As[(4 * kq + 0) * LDSM + m] = v.x;
        As[(4 * kq + 1) * LDSM + m] = v.y;
        As[(4 * kq + 2) * LDSM + m] = v.z;
        As[(4 * kq + 3) * LDSM + m] = v.w;
    }

    float sqa[8]; int labA[8];
    #pragma unroll
    for (int i = 0; i < 8; i++) {
        int r = row0 + ty * 8 + i;
        sqa[i] = g_sqnorm[r];
        labA[i] = g_lab[r];
    }
    float hp[8], hn[8];
    #pragma unroll
    for (int i = 0; i < 8; i++) { hp[i] = 0.f; hn[i] = __int_as_float(0x7f800000); }

    const int tiles_per_split = (NROWS / BN) / SPLITS;
    const int ct0 = blockIdx.y * tiles_per_split;

    for (int ct = ct0; ct < ct0 + tiles_per_split; ++ct) {
        const int col0 = ct * BN;
        __syncthreads();   // protect Bs/s_sqb from readers of the previous tile
        for (int idx = tid; idx < BN * (DDIM / 4); idx += 256) {
            int m = idx & (BN - 1), kq = idx >> 7;
            float4 v = *reinterpret_cast<const float4*>(X + (col0 + m) * DDIM + kq * 4);
            Bs[(4 * kq + 0) * LDSM + m] = v.x;
            Bs[(4 * kq + 1) * LDSM + m] = v.y;
            Bs[(4 * kq + 2) * LDSM + m] = v.z;
            Bs[(4 * kq + 3) * LDSM + m] = v.w;
        }
        if (tid < BN) {
            s_sqb[tid] = g_sqnorm[col0 + tid];
            s_lab[tid] = g_lab[col0 + tid];
        }
        __syncthreads();

        float acc[8][8];
        #pragma unroll
        for (int i = 0; i < 8; i++)
            #pragma unroll
            for (int j = 0; j < 8; j++) acc[i][j] = 0.f;

        #pragma unroll 4
        for (int k = 0; k < DDIM; ++k) {
            float4 a0 = *reinterpret_cast<const float4*>(&As[k * LDSM + ty * 8]);
            float4 a1 = *reinterpret_cast<const float4*>(&As[k * LDSM + ty * 8 + 4]);
            float4 b0 = *reinterpret_cast<const float4*>(&Bs[k * LDSM + tx * 8]);
            float4 b1 = *reinterpret_cast<const float4*>(&Bs[k * LDSM + tx * 8 + 4]);
            float a[8] = {a0.x, a0.y, a0.z, a0.w, a1.x, a1.y, a1.z, a1.w};
            float b[8] = {b0.x, b0.y, b0.z, b0.w, b1.x, b1.y, b1.z, b1.w};
            #pragma unroll
            for (int i = 0; i < 8; i++)
                #pragma unroll
                for (int j = 0; j < 8; j++)
                    acc[i][j] = fmaf(a[i], b[j], acc[i][j]);
        }

        // Epilogue: squared distances + predicated hard mining (sqrt deferred).
        float sqb[8]; int labB[8];
        #pragma unroll
        for (int j = 0; j < 8; j++) {
            sqb[j] = s_sqb[tx * 8 + j];
            labB[j] = s_lab[tx * 8 + j];
        }
        #pragma unroll
        for (int i = 0; i < 8; i++) {
            #pragma unroll
            for (int j = 0; j < 8; j++) {
                float d2 = fmaxf(fmaf(-2.f, acc[i][j], sqa[i] + sqb[j]), 0.f);
                if (labA[i] == labB[j]) hp[i] = fmaxf(hp[i], d2);
                else                    hn[i] = fminf(hn[i], d2);
            }
        }
    }

    // Block-level reduction across the 16 tx threads sharing each row, then global.
    __syncthreads();
    unsigned* s_hp = (unsigned*)smem;          // reuse As space
    unsigned* s_hn = s_hp + BM;
    if (tid < BM) { s_hp[tid] = 0u; s_hn[tid] = 0x7f800000u; }
    __syncthreads();
    #pragma unroll
    for (int i = 0; i < 8; i++) {
        int r = ty * 8 + i;
        atomicMax(&s_hp[r], __float_as_uint(hp[i]));
        atomicMin(&s_hn[r], __float_as_uint(hn[i]));
    }
    __syncthreads();
    if (tid < BM) {
        atomicMax(&g_hp[row0 + tid], s_hp[tid]);
        atomicMin(&g_hn[row0 + tid], s_hn[tid]);
    }
}

// -------- final mean(relu(sqrt(hp)-sqrt(hn)+margin)) --------
__global__ void finalize_kernel(float* __restrict__ out) {
    __shared__ float red[32];
    int tid = threadIdx.x;
    float s = 0.f;
    for (int r = tid; r < NROWS; r += 1024) {
        float hp = sqrtf(__uint_as_float(g_hp[r]));
        float hn = sqrtf(__uint_as_float(g_hn[r]));    // +inf -> loss 0, matches reference
        s += fmaxf(hp - hn + MARGIN, 0.f);
    }
    #pragma unroll
    for (int o = 16; o; o >>= 1) s += __shfl_xor_sync(0xffffffffu, s, o);
    if ((tid & 31) == 0) red[tid >> 5] = s;
    __syncthreads();
    if (tid < 32) {
        float v = red[tid];
        #pragma unroll
        for (int o = 16; o; o >>= 1) v += __shfl_xor_sync(0xffffffffu, v, o);
        if (tid == 0) out[0] = v * (1.0f / (float)NROWS);
    }
}

extern "C" void kernel_launch(void* const* d_in, const int* in_sizes, int n_in,
                              void* d_out, int out_size) {
    const float* X    = (const float*)d_in[0];
    const int*  lab32 = (const int*)d_in[1];   // raw view; detect kernel resolves dtype
    float* out = (float*)d_out;

    const int smem_bytes = (2 * DDIM * LDSM + BN) * (int)sizeof(float) + BN * (int)sizeof(int);
    cudaFuncSetAttribute(tile_kernel, cudaFuncAttributeMaxDynamicSharedMemorySize, smem_bytes);

    detect_kernel<<<1, 256>>>(lab32);
    convert_kernel<<<NROWS / 256, 256>>>(lab32);
    norms_kernel<<<NROWS / 8, 256>>>(X);

    dim3 grid(NROWS / BM, SPLITS);
    tile_kernel<<<grid, 256, smem_bytes>>>(X);

    finalize_kernel<<<1, 1024>>>(out);
}

// round 5
// speedup vs baseline: 5.4189x; 5.4189x over previous
#include <cuda_runtime.h>
#include <cuda_fp16.h>
#include <cstdint>

#define NROWS  8192
#define DDIM   128
#define BM     128
#define BN     128
#define SPLITY 2
#define TILES_PER_CTA ((NROWS / BN) / SPLITY)   // 32
#define MARGIN 0.3f

// ---------------- device scratch (no allocations allowed) ----------------
__device__ int      g_mode64;
__device__ int      g_lab[NROWS];
__device__ unsigned g_hp[NROWS];
__device__ unsigned g_hn[NROWS];
__device__ __align__(16) float2 g_meta[NROWS];        // {label bits, sqnorm}
__device__ __align__(16) __half g_X16[NROWS * DDIM];

// ---------------- helpers ----------------
__device__ __forceinline__ uint32_t smem_u32(const void* p) {
    uint32_t a;
    asm("{ .reg .u64 t; cvta.to.shared.u64 t, %1; cvt.u32.u64 %0, t; }" : "=r"(a) : "l"(p));
    return a;
}
__device__ __forceinline__ void cp_async16(uint32_t s, const void* g) {
    asm volatile("cp.async.cg.shared.global [%0], [%1], 16;" :: "r"(s), "l"(g));
}
#define CP_COMMIT() asm volatile("cp.async.commit_group;" ::: "memory")
#define CP_WAIT0()  asm volatile("cp.async.wait_group 0;" ::: "memory")

__device__ __forceinline__ void ldsm_x4(uint32_t* d, uint32_t addr) {
    asm volatile("ldmatrix.sync.aligned.m8n8.x4.shared.b16 {%0,%1,%2,%3}, [%4];"
                 : "=r"(d[0]), "=r"(d[1]), "=r"(d[2]), "=r"(d[3]) : "r"(addr));
}
__device__ __forceinline__ void mma16816(float* c, const uint32_t* a, uint32_t b0, uint32_t b1) {
    asm volatile("mma.sync.aligned.m16n8k16.row.col.f32.f16.f16.f32 "
                 "{%0,%1,%2,%3}, {%4,%5,%6,%7}, {%8,%9}, {%0,%1,%2,%3};"
                 : "+f"(c[0]), "+f"(c[1]), "+f"(c[2]), "+f"(c[3])
                 : "r"(a[0]), "r"(a[1]), "r"(a[2]), "r"(a[3]), "r"(b0), "r"(b1));
}

// swizzled byte offset within a 128x128 fp16 tile: row r (256B rows), 16B chunk c16
#define SWZ(r, c) ((uint32_t)((r) * 256 + ((((c) ^ ((r) & 7))) * 16)))

// ---------------- smem layout (bytes) ----------------
#define SM_A   0
#define SM_B0  32768
#define SM_B1  65536
#define SM_M0  98304            // 128 x float2
#define SM_M1  99328
#define SM_TOT 100352

// ---------------- labels: int64 vs int32 detect + normalize ----------------
__global__ void detect_kernel(const int* __restrict__ lab32) {
    __shared__ unsigned red[8];
    unsigned o = 0;
    for (int i = threadIdx.x; i < 2048; i += 256) o |= (unsigned)lab32[2 * i + 1];
    #pragma unroll
    for (int s = 16; s; s >>= 1) o |= __shfl_xor_sync(0xffffffffu, o, s);
    if ((threadIdx.x & 31) == 0) red[threadIdx.x >> 5] = o;
    __syncthreads();
    if (threadIdx.x == 0) {
        unsigned t = 0;
        #pragma unroll
        for (int i = 0; i < 8; i++) t |= red[i];
        g_mode64 = (t == 0) ? 1 : 0;
    }
}
__global__ void convert_kernel(const int* __restrict__ lab32) {
    int i = blockIdx.x * blockDim.x + threadIdx.x;
    if (i < NROWS) g_lab[i] = g_mode64 ? lab32[2 * i] : lab32[i];
}

// ---------------- norms (fp32), meta pack, scratch init ----------------
__global__ void norms_kernel(const float* __restrict__ X) {
    int w = threadIdx.x >> 5, lane = threadIdx.x & 31;
    int row = blockIdx.x * 8 + w;
    const float* xr = X + row * DDIM;
    float s = 0.f;
    #pragma unroll
    for (int k = lane; k < DDIM; k += 32) { float v = xr[k]; s = fmaf(v, v, s); }
    #pragma unroll
    for (int o = 16; o; o >>= 1) s += __shfl_xor_sync(0xffffffffu, s, o);
    if (lane == 0) {
        float2 m; m.x = __int_as_float(g_lab[row]); m.y = s;
        g_meta[row] = m;
        g_hp[row] = 0u;
        g_hn[row] = 0x7f800000u;
    }
}
__global__ void tofp16_kernel(const float* __restrict__ X) {
    int i = blockIdx.x * blockDim.x + threadIdx.x;
    float2 v = reinterpret_cast<const float2*>(X)[i];
    reinterpret_cast<__half2*>(g_X16)[i] = __floats2half2_rn(v.x, v.y);
}

// ---------------- fused HMMA Gram + hard mining ----------------
__global__ __launch_bounds__(256, 1) void mma_kernel() {
    extern __shared__ char smem[];
    const uint32_t sb = smem_u32(smem);
    const int tid = threadIdx.x, wid = tid >> 5, lane = tid & 31;
    const int warpM = wid & 1, warpN = wid >> 1;
    const int row0 = blockIdx.x * BM;
    const int ct0 = blockIdx.y * TILES_PER_CTA;

    // ---- initial async loads: A tile, B tile 0, meta 0 ----
    #pragma unroll
    for (int i = 0; i < 8; i++) {
        int lin = tid + i * 256;
        int r = lin >> 4, c = lin & 15;
        uint32_t so = SWZ(r, c);
        cp_async16(sb + SM_A + so, (const char*)(g_X16 + (row0 + r) * DDIM) + c * 16);
        cp_async16(sb + SM_B0 + so, (const char*)(g_X16 + (ct0 * BN + r) * DDIM) + c * 16);
    }
    if (tid < 64)
        cp_async16(sb + SM_M0 + tid * 16, (const char*)(g_meta + ct0 * BN) + tid * 16);
    CP_COMMIT();

    // ---- per-thread row meta (8 rows owned by this thread) ----
    float sqa[8]; int labA[8];
    {
        int rbase = row0 + warpM * 64 + (lane >> 2);
        #pragma unroll
        for (int mf = 0; mf < 4; mf++) {
            float2 m0 = g_meta[rbase + mf * 16];
            float2 m1 = g_meta[rbase + mf * 16 + 8];
            sqa[mf * 2]     = m0.y; labA[mf * 2]     = __float_as_int(m0.x);
            sqa[mf * 2 + 1] = m1.y; labA[mf * 2 + 1] = __float_as_int(m1.x);
        }
    }
    float hp[8], hn[8];
    #pragma unroll
    for (int i = 0; i < 8; i++) { hp[i] = 0.f; hn[i] = __int_as_float(0x7f800000); }

    // ldmatrix row-base addresses (swizzle XOR term is lane&7 for every fragment)
    const int hi = lane >> 4, sw = lane & 7, rl = lane & 15;
    uint32_t aRow[4], bRowRel[2];
    #pragma unroll
    for (int mf = 0; mf < 4; mf++) aRow[mf] = sb + SM_A + (uint32_t)(warpM * 64 + mf * 16 + rl) * 256;
    #pragma unroll
    for (int pr = 0; pr < 2; pr++) bRowRel[pr] = (uint32_t)(warpN * 32 + pr * 16 + rl) * 256;

    CP_WAIT0();
    __syncthreads();

    for (int t = 0; t < TILES_PER_CTA; t++) {
        const uint32_t bufB = (t & 1) ? SM_B1 : SM_B0;
        const uint32_t bufM = (t & 1) ? SM_M1 : SM_M0;

        // prefetch next B + meta into the other buffer
        if (t + 1 < TILES_PER_CTA) {
            const int c0 = (ct0 + t + 1) * BN;
            const uint32_t nB = (t & 1) ? SM_B0 : SM_B1;
            const uint32_t nM = (t & 1) ? SM_M0 : SM_M1;
            #pragma unroll
            for (int i = 0; i < 8; i++) {
                int lin = tid + i * 256;
                int r = lin >> 4, c = lin & 15;
                cp_async16(sb + nB + SWZ(r, c), (const char*)(g_X16 + (c0 + r) * DDIM) + c * 16);
            }
            if (tid < 64)
                cp_async16(sb + nM + tid * 16, (const char*)(g_meta + c0) + tid * 16);
            CP_COMMIT();
        }

        // ---- GEMM: 8 k-chunks x (4 A-frags, 2 B-frag-pairs, 16 mma) ----
        float acc[4][4][4];
        #pragma unroll
        for (int mf = 0; mf < 4; mf++)
            #pragma unroll
            for (int nf = 0; nf < 4; nf++)
                #pragma unroll
                for (int q = 0; q < 4; q++) acc[mf][nf][q] = 0.f;

        #pragma unroll
        for (int kc = 0; kc < 8; kc++) {
            const uint32_t cx = (uint32_t)(((2 * kc + hi) ^ sw) * 16);
            uint32_t a[4][4], b[2][4];
            #pragma unroll
            for (int mf = 0; mf < 4; mf++) ldsm_x4(a[mf], aRow[mf] + cx);
            #pragma unroll
            for (int pr = 0; pr < 2; pr++) ldsm_x4(b[pr], sb + bufB + bRowRel[pr] + cx);
            #pragma unroll
            for (int mf = 0; mf < 4; mf++) {
                mma16816(acc[mf][0], a[mf], b[0][0], b[0][2]);
                mma16816(acc[mf][1], a[mf], b[0][1], b[0][3]);
                mma16816(acc[mf][2], a[mf], b[1][0], b[1][2]);
                mma16816(acc[mf][3], a[mf], b[1][1], b[1][3]);
            }
        }

        // ---- epilogue: squared distances + mining (registers only) ----
        const float2* meta = reinterpret_cast<const float2*>(smem + bufM);
        #pragma unroll
        for (int nf = 0; nf < 4; nf++) {
            const int cb = warpN * 32 + nf * 8 + (lane & 3) * 2;
            const float2 mv0 = meta[cb], mv1 = meta[cb + 1];
            const int lb0 = __float_as_int(mv0.x), lb1 = __float_as_int(mv1.x);
            #pragma unroll
            for (int mf = 0; mf < 4; mf++) {
                const int rlo = mf * 2, rhi = mf * 2 + 1;
                float d00 = fmaxf(fmaf(-2.f, acc[mf][nf][0], sqa[rlo] + mv0.y), 0.f);
                float d01 = fmaxf(fmaf(-2.f, acc[mf][nf][1], sqa[rlo] + mv1.y), 0.f);
                float d10 = fmaxf(fmaf(-2.f, acc[mf][nf][2], sqa[rhi] + mv0.y), 0.f);
                float d11 = fmaxf(fmaf(-2.f, acc[mf][nf][3], sqa[rhi] + mv1.y), 0.f);
                if (lb0 == labA[rlo]) hp[rlo] = fmaxf(hp[rlo], d00); else hn[rlo] = fminf(hn[rlo], d00);
                if (lb1 == labA[rlo]) hp[rlo] = fmaxf(hp[rlo], d01); else hn[rlo] = fminf(hn[rlo], d01);
                if (lb0 == labA[rhi]) hp[rhi] = fmaxf(hp[rhi], d10); else hn[rhi] = fminf(hn[rhi], d10);
                if (lb1 == labA[rhi]) hp[rhi] = fmaxf(hp[rhi], d11); else hn[rhi] = fminf(hn[rhi], d11);
            }
        }

        if (t + 1 < TILES_PER_CTA) { CP_WAIT0(); __syncthreads(); }
    }

    // ---- reduce across the 4 lanes sharing each row (lane&3 = column group) ----
    #pragma unroll
    for (int i = 0; i < 8; i++) {
        hp[i] = fmaxf(hp[i], __shfl_xor_sync(0xffffffffu, hp[i], 1));
        hp[i] = fmaxf(hp[i], __shfl_xor_sync(0xffffffffu, hp[i], 2));
        hn[i] = fminf(hn[i], __shfl_xor_sync(0xffffffffu, hn[i], 1));
        hn[i] = fminf(hn[i], __shfl_xor_sync(0xffffffffu, hn[i], 2));
    }

    // ---- smem reduction across warps, then global atomics ----
    __syncthreads();
    unsigned* s_hp = reinterpret_cast<unsigned*>(smem);
    unsigned* s_hn = s_hp + BM;
    if (tid < BM) { s_hp[tid] = 0u; s_hn[tid] = 0x7f800000u; }
    __syncthreads();
    if ((lane & 3) == 0) {
        #pragma unroll
        for (int i = 0; i < 8; i++) {
            int r = warpM * 64 + (i >> 1) * 16 + (i & 1) * 8 + (lane >> 2);
            atomicMax(&s_hp[r], __float_as_uint(hp[i]));
            atomicMin(&s_hn[r], __float_as_uint(hn[i]));
        }
    }
    __syncthreads();
    if (tid < BM) {
        atomicMax(&g_hp[row0 + tid], s_hp[tid]);
        atomicMin(&g_hn[row0 + tid], s_hn[tid]);
    }
}

// ---------------- final mean(relu(sqrt(hp)-sqrt(hn)+margin)) ----------------
__global__ void finalize_kernel(float* __restrict__ out) {
    __shared__ float red[32];
    int tid = threadIdx.x;
    float s = 0.f;
    for (int r = tid; r < NROWS; r += 1024) {
        float hp = sqrtf(__uint_as_float(g_hp[r]));
        float hn = sqrtf(__uint_as_float(g_hn[r]));
        s += fmaxf(hp - hn + MARGIN, 0.f);
    }
    #pragma unroll
    for (int o = 16; o; o >>= 1) s += __shfl_xor_sync(0xffffffffu, s, o);
    if ((tid & 31) == 0) red[tid >> 5] = s;
    __syncthreads();
    if (tid < 32) {
        float v = red[tid];
        #pragma unroll
        for (int o = 16; o; o >>= 1) v += __shfl_xor_sync(0xffffffffu, v, o);
        if (tid == 0) out[0] = v * (1.0f / (float)NROWS);
    }
}

extern "C" void kernel_launch(void* const* d_in, const int* in_sizes, int n_in,
                              void* d_out, int out_size) {
    const float* X   = (const float*)d_in[0];
    const int* lab32 = (const int*)d_in[1];
    float* out = (float*)d_out;

    cudaFuncSetAttribute(mma_kernel, cudaFuncAttributeMaxDynamicSharedMemorySize, SM_TOT);

    detect_kernel<<<1, 256>>>(lab32);
    convert_kernel<<<NROWS / 256, 256>>>(lab32);
    norms_kernel<<<NROWS / 8, 256>>>(X);
    tofp16_kernel<<<(NROWS * DDIM / 2) / 256, 256>>>(X);

    dim3 grid(NROWS / BM, SPLITY);
    mma_kernel<<<grid, 256, SM_TOT>>>();

    finalize_kernel<<<1, 1024>>>(out);
}

// round 7
// speedup vs baseline: 6.0126x; 1.1095x over previous
#include <cuda_runtime.h>
#include <cuda_fp16.h>
#include <cstdint>

#define NROWS  8192
#define DDIM   128
#define BM     128
#define BN     128
#define SPLITY 2
#define TILES_PER_CTA ((NROWS / BN) / SPLITY)   // 32
#define MARGIN 0.3f

// ---------------- device scratch (no allocations allowed) ----------------
__device__ int      g_mode64;
__device__ unsigned g_hp[NROWS];
__device__ unsigned g_hn[NROWS];
__device__ __align__(16) float2 g_meta[NROWS];        // {label bits, sqnorm}
__device__ __align__(16) __half g_X16[NROWS * DDIM];

// ---------------- helpers ----------------
__device__ __forceinline__ uint32_t smem_u32(const void* p) {
    uint32_t a;
    asm("{ .reg .u64 t; cvta.to.shared.u64 t, %1; cvt.u32.u64 %0, t; }" : "=r"(a) : "l"(p));
    return a;
}
__device__ __forceinline__ void cp_async16(uint32_t s, const void* g) {
    asm volatile("cp.async.cg.shared.global [%0], [%1], 16;" :: "r"(s), "l"(g));
}
#define CP_COMMIT() asm volatile("cp.async.commit_group;" ::: "memory")
#define CP_WAIT0()  asm volatile("cp.async.wait_group 0;" ::: "memory")

__device__ __forceinline__ void ldsm_x4(uint32_t* d, uint32_t addr) {
    asm volatile("ldmatrix.sync.aligned.m8n8.x4.shared.b16 {%0,%1,%2,%3}, [%4];"
                 : "=r"(d[0]), "=r"(d[1]), "=r"(d[2]), "=r"(d[3]) : "r"(addr));
}
__device__ __forceinline__ void mma16816(float* c, const uint32_t* a, uint32_t b0, uint32_t b1) {
    asm volatile("mma.sync.aligned.m16n8k16.row.col.f32.f16.f16.f32 "
                 "{%0,%1,%2,%3}, {%4,%5,%6,%7}, {%8,%9}, {%0,%1,%2,%3};"
                 : "+f"(c[0]), "+f"(c[1]), "+f"(c[2]), "+f"(c[3])
                 : "r"(a[0]), "r"(a[1]), "r"(a[2]), "r"(a[3]), "r"(b0), "r"(b1));
}

// swizzled byte offset within a 128x128 fp16 tile: row r (256B rows), 16B chunk c16
#define SWZ(r, c) ((uint32_t)((r) * 256 + ((((c) ^ ((r) & 7))) * 16)))

// ---------------- smem layout (bytes) ----------------
#define SM_A   0
#define SM_B0  32768
#define SM_B1  65536
#define SM_M0  98304            // 128 x float2
#define SM_M1  99328
#define SM_TOT 100352

// ---------------- labels: int64 vs int32 detect ----------------
__global__ void detect_kernel(const int* __restrict__ lab32) {
    __shared__ unsigned red[8];
    unsigned o = 0;
    for (int i = threadIdx.x; i < 2048; i += 256) o |= (unsigned)lab32[2 * i + 1];
    #pragma unroll
    for (int s = 16; s; s >>= 1) o |= __shfl_xor_sync(0xffffffffu, o, s);
    if ((threadIdx.x & 31) == 0) red[threadIdx.x >> 5] = o;
    __syncthreads();
    if (threadIdx.x == 0) {
        unsigned t = 0;
        #pragma unroll
        for (int i = 0; i < 8; i++) t |= red[i];
        g_mode64 = (t == 0) ? 1 : 0;
    }
}

// ---------------- fused prep: labels + norms + meta + fp16 + init ----------------
// one warp per row group: 128 blocks x 8 warps x 8 rows
__global__ __launch_bounds__(256) void prep_kernel(const float* __restrict__ X,
                                                   const int* __restrict__ lab32) {
    const int wid = threadIdx.x >> 5, lane = threadIdx.x & 31;
    const int rowbase = blockIdx.x * 64 + wid * 8;
    const int m64 = g_mode64;
    #pragma unroll
    for (int r8 = 0; r8 < 8; r8++) {
        const int row = rowbase + r8;
        float4 v = reinterpret_cast<const float4*>(X + row * DDIM)[lane];
        float s = v.x * v.x;
        s = fmaf(v.y, v.y, s);
        s = fmaf(v.z, v.z, s);
        s = fmaf(v.w, v.w, s);
        #pragma unroll
        for (int o = 16; o; o >>= 1) s += __shfl_xor_sync(0xffffffffu, s, o);
        __half2 h0 = __floats2half2_rn(v.x, v.y);
        __half2 h1 = __floats2half2_rn(v.z, v.w);
        __half2* dst = reinterpret_cast<__half2*>(g_X16 + row * DDIM) + lane * 2;
        dst[0] = h0;
        dst[1] = h1;
        if (lane == 0) {
            int lab = m64 ? lab32[2 * row] : lab32[row];
            float2 m; m.x = __int_as_float(lab); m.y = s;
            g_meta[row] = m;
            g_hp[row] = 0u;
            g_hn[row] = 0x7f800000u;
        }
    }
}

// ---------------- fused HMMA Gram + hard mining (A frags in registers) ----------------
__global__ __launch_bounds__(256, 1) void mma_kernel() {
    extern __shared__ char smem[];
    const uint32_t sb = smem_u32(smem);
    const int tid = threadIdx.x, wid = tid >> 5, lane = tid & 31;
    const int warpM = wid & 3, warpN = wid >> 2;     // 4 M-warps x 2 N-warps, warp tile 32x64
    const int row0 = blockIdx.x * BM;
    const int ct0 = blockIdx.y * TILES_PER_CTA;

    // ---- initial async loads: A tile, B tile 0, meta 0 ----
    #pragma unroll
    for (int i = 0; i < 8; i++) {
        int lin = tid + i * 256;
        int r = lin >> 4, c = lin & 15;
        uint32_t so = SWZ(r, c);
        cp_async16(sb + SM_A + so, (const char*)(g_X16 + (row0 + r) * DDIM) + c * 16);
        cp_async16(sb + SM_B0 + so, (const char*)(g_X16 + (ct0 * BN + r) * DDIM) + c * 16);
    }
    if (tid < 64)
        cp_async16(sb + SM_M0 + tid * 16, (const char*)(g_meta + ct0 * BN) + tid * 16);
    CP_COMMIT();

    // ---- per-thread row meta (4 rows owned by this thread) ----
    float sqa[4]; int labA[4];
    {
        int rbase = row0 + warpM * 32 + (lane >> 2);
        #pragma unroll
        for (int mf = 0; mf < 2; mf++) {
            float2 m0 = g_meta[rbase + mf * 16];
            float2 m1 = g_meta[rbase + mf * 16 + 8];
            sqa[mf * 2]     = m0.y; labA[mf * 2]     = __float_as_int(m0.x);
            sqa[mf * 2 + 1] = m1.y; labA[mf * 2 + 1] = __float_as_int(m1.x);
        }
    }
    float hp[4], hn[4];
    #pragma unroll
    for (int i = 0; i < 4; i++) { hp[i] = 0.f; hn[i] = __int_as_float(0x7f800000); }

    // ldmatrix bases (swizzle XOR term is lane&7 for every fragment)
    const int hi = lane >> 4, sw = lane & 7, rl = lane & 15;
    uint32_t aRowBase[2], bRowRel[4];
    #pragma unroll
    for (int mf = 0; mf < 2; mf++) aRowBase[mf] = sb + SM_A + (uint32_t)(warpM * 32 + mf * 16 + rl) * 256;
    #pragma unroll
    for (int bn = 0; bn < 4; bn++) bRowRel[bn] = (uint32_t)(warpN * 64 + bn * 16 + rl) * 256;

    CP_WAIT0();
    __syncthreads();

    // ---- extract ALL A fragments into registers (held for the whole kernel) ----
    uint32_t a[2][8][4];
    #pragma unroll
    for (int kc = 0; kc < 8; kc++) {
        const uint32_t cx = (uint32_t)(((2 * kc + hi) ^ sw) * 16);
        #pragma unroll
        for (int mf = 0; mf < 2; mf++) ldsm_x4(a[mf][kc], aRowBase[mf] + cx);
    }

    for (int t = 0; t < TILES_PER_CTA; t++) {
        const uint32_t bufB = (t & 1) ? SM_B1 : SM_B0;
        const uint32_t bufM = (t & 1) ? SM_M1 : SM_M0;

        // prefetch next B + meta into the other buffer
        if (t + 1 < TILES_PER_CTA) {
            const int c0 = (ct0 + t + 1) * BN;
            const uint32_t nB = (t & 1) ? SM_B0 : SM_B1;
            const uint32_t nM = (t & 1) ? SM_M0 : SM_M1;
            #pragma unroll
            for (int i = 0; i < 8; i++) {
                int lin = tid + i * 256;
                int r = lin >> 4, c = lin & 15;
                cp_async16(sb + nB + SWZ(r, c), (const char*)(g_X16 + (c0 + r) * DDIM) + c * 16);
            }
            if (tid < 64)
                cp_async16(sb + nM + tid * 16, (const char*)(g_meta + c0) + tid * 16);
            CP_COMMIT();
        }

        // ---- GEMM: 8 k-chunks x (4 B ldsm.x4 + 16 mma); A comes from registers ----
        float acc[2][8][4];
        #pragma unroll
        for (int mf = 0; mf < 2; mf++)
            #pragma unroll
            for (int nf = 0; nf < 8; nf++)
                #pragma unroll
                for (int q = 0; q < 4; q++) acc[mf][nf][q] = 0.f;

        #pragma unroll
        for (int kc = 0; kc < 8; kc++) {
            const uint32_t cx = (uint32_t)(((2 * kc + hi) ^ sw) * 16);
            uint32_t b[4][4];
            #pragma unroll
            for (int bn = 0; bn < 4; bn++) ldsm_x4(b[bn], sb + bufB + bRowRel[bn] + cx);
            #pragma unroll
            for (int mf = 0; mf < 2; mf++) {
                #pragma unroll
                for (int bn = 0; bn < 4; bn++) {
                    mma16816(acc[mf][bn * 2],     a[mf][kc], b[bn][0], b[bn][2]);
                    mma16816(acc[mf][bn * 2 + 1], a[mf][kc], b[bn][1], b[bn][3]);
                }
            }
        }

        // ---- epilogue: squared distances + mining (registers only) ----
        const float2* meta = reinterpret_cast<const float2*>(smem + bufM);
        #pragma unroll
        for (int nf = 0; nf < 8; nf++) {
            const int cb = warpN * 64 + nf * 8 + (lane & 3) * 2;
            const float2 mv0 = meta[cb], mv1 = meta[cb + 1];
            const int lb0 = __float_as_int(mv0.x), lb1 = __float_as_int(mv1.x);
            #pragma unroll
            for (int mf = 0; mf < 2; mf++) {
                const int rlo = mf * 2, rhi = mf * 2 + 1;
                float d00 = fmaxf(fmaf(-2.f, acc[mf][nf][0], sqa[rlo] + mv0.y), 0.f);
                float d01 = fmaxf(fmaf(-2.f, acc[mf][nf][1], sqa[rlo] + mv1.y), 0.f);
                float d10 = fmaxf(fmaf(-2.f, acc[mf][nf][2], sqa[rhi] + mv0.y), 0.f);
                float d11 = fmaxf(fmaf(-2.f, acc[mf][nf][3], sqa[rhi] + mv1.y), 0.f);
                if (lb0 == labA[rlo]) hp[rlo] = fmaxf(hp[rlo], d00); else hn[rlo] = fminf(hn[rlo], d00);
                if (lb1 == labA[rlo]) hp[rlo] = fmaxf(hp[rlo], d01); else hn[rlo] = fminf(hn[rlo], d01);
                if (lb0 == labA[rhi]) hp[rhi] = fmaxf(hp[rhi], d10); else hn[rhi] = fminf(hn[rhi], d10);
                if (lb1 == labA[rhi]) hp[rhi] = fmaxf(hp[rhi], d11); else hn[rhi] = fminf(hn[rhi], d11);
            }
        }

        if (t + 1 < TILES_PER_CTA) { CP_WAIT0(); __syncthreads(); }
    }

    // ---- reduce across the 4 lanes sharing each row (lane&3 = column group) ----
    #pragma unroll
    for (int i = 0; i < 4; i++) {
        hp[i] = fmaxf(hp[i], __shfl_xor_sync(0xffffffffu, hp[i], 1));
        hp[i] = fmaxf(hp[i], __shfl_xor_sync(0xffffffffu, hp[i], 2));
        hn[i] = fminf(hn[i], __shfl_xor_sync(0xffffffffu, hn[i], 1));
        hn[i] = fminf(hn[i], __shfl_xor_sync(0xffffffffu, hn[i], 2));
    }

    // ---- smem reduction across the 2 N-warps, then global atomics ----
    __syncthreads();
    unsigned* s_hp = reinterpret_cast<unsigned*>(smem);
    unsigned* s_hn = s_hp + BM;
    if (tid < BM) { s_hp[tid] = 0u; s_hn[tid] = 0x7f800000u; }
    __syncthreads();
    if ((lane & 3) == 0) {
        #pragma unroll
        for (int i = 0; i < 4; i++) {
            int r = warpM * 32 + (i >> 1) * 16 + (i & 1) * 8 + (lane >> 2);
            atomicMax(&s_hp[r], __float_as_uint(hp[i]));
            atomicMin(&s_hn[r], __float_as_uint(hn[i]));
        }
    }
    __syncthreads();
    if (tid < BM) {
        atomicMax(&g_hp[row0 + tid], s_hp[tid]);
        atomicMin(&g_hn[row0 + tid], s_hn[tid]);
    }
}

// ---------------- final mean(relu(sqrt(hp)-sqrt(hn)+margin)) ----------------
__global__ void finalize_kernel(float* __restrict__ out) {
    __shared__ float red[32];
    int tid = threadIdx.x;
    float s = 0.f;
    for (int r = tid; r < NROWS; r += 1024) {
        float hp = sqrtf(__uint_as_float(g_hp[r]));
        float hn = sqrtf(__uint_as_float(g_hn[r]));
        s += fmaxf(hp - hn + MARGIN, 0.f);
    }
    #pragma unroll
    for (int o = 16; o; o >>= 1) s += __shfl_xor_sync(0xffffffffu, s, o);
    if ((tid & 31) == 0) red[tid >> 5] = s;
    __syncthreads();
    if (tid < 32) {
        float v = red[tid];
        #pragma unroll
        for (int o = 16; o; o >>= 1) v += __shfl_xor_sync(0xffffffffu, v, o);
        if (tid == 0) out[0] = v * (1.0f / (float)NROWS);
    }
}

extern "C" void kernel_launch(void* const* d_in, const int* in_sizes, int n_in,
                              void* d_out, int out_size) {
    const float* X   = (const float*)d_in[0];
    const int* lab32 = (const int*)d_in[1];
    float* out = (float*)d_out;

    cudaFuncSetAttribute(mma_kernel, cudaFuncAttributeMaxDynamicSharedMemorySize, SM_TOT);

    detect_kernel<<<1, 256>>>(lab32);
    prep_kernel<<<NROWS / 64, 256>>>(X, lab32);

    dim3 grid(NROWS / BM, SPLITY);
    mma_kernel<<<grid, 256, SM_TOT>>>();

    finalize_kernel<<<1, 1024>>>(out);
}

// round 8
// speedup vs baseline: 6.3051x; 1.0487x over previous
#include <cuda_runtime.h>
#include <cuda_fp16.h>
#include <cstdint>

#define NROWS  8192
#define DDIM   128
#define BM     128
#define NB     (NROWS / BM)              // 64
#define NPAIRS (NB * (NB + 1) / 2)       // 2080
#define GRID_MMA (NPAIRS / 2)            // 1040
#define MARGIN 0.3f

// ---------------- device scratch (no allocations allowed) ----------------
__device__ unsigned g_hp[NROWS];
__device__ unsigned g_hn[NROWS];
__device__ __align__(16) float2 g_meta[NROWS];        // {label bits, sqnorm}
__device__ __align__(16) __half g_X16[NROWS * DDIM];
__device__ unsigned long long g_isum;
__device__ unsigned g_done;

// ---------------- helpers ----------------
__device__ __forceinline__ uint32_t smem_u32(const void* p) {
    uint32_t a;
    asm("{ .reg .u64 t; cvta.to.shared.u64 t, %1; cvt.u32.u64 %0, t; }" : "=r"(a) : "l"(p));
    return a;
}
__device__ __forceinline__ void cp_async16(uint32_t s, const void* g) {
    asm volatile("cp.async.cg.shared.global [%0], [%1], 16;" :: "r"(s), "l"(g));
}
#define CP_COMMIT() asm volatile("cp.async.commit_group;" ::: "memory")
#define CP_WAIT(n)  asm volatile("cp.async.wait_group %0;" :: "n"(n) : "memory")

__device__ __forceinline__ void ldsm_x4(uint32_t* d, uint32_t addr) {
    asm volatile("ldmatrix.sync.aligned.m8n8.x4.shared.b16 {%0,%1,%2,%3}, [%4];"
                 : "=r"(d[0]), "=r"(d[1]), "=r"(d[2]), "=r"(d[3]) : "r"(addr));
}
__device__ __forceinline__ void mma16816(float* c, const uint32_t* a, uint32_t b0, uint32_t b1) {
    asm volatile("mma.sync.aligned.m16n8k16.row.col.f32.f16.f16.f32 "
                 "{%0,%1,%2,%3}, {%4,%5,%6,%7}, {%8,%9}, {%0,%1,%2,%3};"
                 : "+f"(c[0]), "+f"(c[1]), "+f"(c[2]), "+f"(c[3])
                 : "r"(a[0]), "r"(a[1]), "r"(a[2]), "r"(a[3]), "r"(b0), "r"(b1));
}

// swizzled byte offset within a 128x128 fp16 tile: row r (256B rows), 16B chunk c16
#define SWZ(r, c) ((uint32_t)((r) * 256 + ((((c) ^ ((r) & 7))) * 16)))

// ---------------- smem layout (bytes) ----------------
#define SM_A0   0
#define SM_B0   32768
#define SM_A1   65536
#define SM_B1   98304
#define SM_MA0  131072
#define SM_MB0  132096
#define SM_MA1  133120
#define SM_MB1  134144
#define SM_MINE 135168          // 512 u32: [0:128) rowHP [128:256) rowHN [256:384) colHP [384:512) colHN
#define SM_TOT  137216

// ---------------- fused prep: inline label-width detect + labels + norms + fp16 + init ----------------
__global__ __launch_bounds__(256) void prep_kernel(const float* __restrict__ X,
                                                   const int* __restrict__ lab32) {
    __shared__ unsigned sdet[8];
    __shared__ int smode;
    const int tid = threadIdx.x, wid = tid >> 5, lane = tid & 31;

    // int64-vs-int32 detect: all odd words of first 4096 words zero => int64
    unsigned o = 0;
    for (int i = tid; i < 2048; i += 256) o |= (unsigned)lab32[2 * i + 1];
    #pragma unroll
    for (int s = 16; s; s >>= 1) o |= __shfl_xor_sync(0xffffffffu, o, s);
    if (lane == 0) sdet[wid] = o;
    __syncthreads();
    if (tid == 0) {
        unsigned t = 0;
        #pragma unroll
        for (int k = 0; k < 8; k++) t |= sdet[k];
        smode = (t == 0) ? 1 : 0;
        if (blockIdx.x == 0) { g_isum = 0ull; g_done = 0u; }
    }
    __syncthreads();
    const int m64 = smode;

    const int rowbase = blockIdx.x * 64 + wid * 8;
    #pragma unroll
    for (int r8 = 0; r8 < 8; r8++) {
        const int row = rowbase + r8;
        float4 v = reinterpret_cast<const float4*>(X + row * DDIM)[lane];
        float s = v.x * v.x;
        s = fmaf(v.y, v.y, s);
        s = fmaf(v.z, v.z, s);
        s = fmaf(v.w, v.w, s);
        #pragma unroll
        for (int off = 16; off; off >>= 1) s += __shfl_xor_sync(0xffffffffu, s, off);
        __half2 h0 = __floats2half2_rn(v.x, v.y);
        __half2 h1 = __floats2half2_rn(v.z, v.w);
        __half2* dst = reinterpret_cast<__half2*>(g_X16 + row * DDIM) + lane * 2;
        dst[0] = h0;
        dst[1] = h1;
        if (lane == 0) {
            int lab = m64 ? lab32[2 * row] : lab32[row];
            float2 m; m.x = __int_as_float(lab); m.y = s;
            g_meta[row] = m;
            g_hp[row] = 0u;
            g_hn[row] = 0x7f800000u;
        }
    }
}

// ---------------- symmetric HMMA Gram + dual-direction hard mining ----------------
// CTA handles 2 upper-triangle (i,j) tile pairs; mines rows (block i) and cols (block j).
__global__ __launch_bounds__(256, 1) void mma_kernel() {
    extern __shared__ char smem[];
    const uint32_t sb = smem_u32(smem);
    const int tid = threadIdx.x, wid = tid >> 5, lane = tid & 31;
    const int warpM = wid & 3, warpN = wid >> 2;     // 4 M-warps x 2 N-warps, warp tile 32x64

    // decode two triangular pairs: T(i) = i*(129-i)/2, j = i + p - T(i)
    int ii[2], jj[2];
    {
        const int p0 = blockIdx.x * 2;
        #pragma unroll
        for (int q = 0; q < 2; q++) {
            int p = p0 + q;
            int i = (int)((129.0f - sqrtf(16641.0f - 8.0f * (float)p)) * 0.5f);
            while ((i + 1) * (129 - (i + 1)) / 2 <= p) i++;
            while (i * (129 - i) / 2 > p) i--;
            ii[q] = i;
            jj[q] = i + (p - i * (129 - i) / 2);
        }
    }

    const uint32_t Aoff[2] = {SM_A0, SM_A1}, Boff[2] = {SM_B0, SM_B1};
    const uint32_t MAoff[2] = {SM_MA0, SM_MA1}, MBoff[2] = {SM_MB0, SM_MB1};

    // issue loads for both pairs (group 0 = pair 0, group 1 = pair 1)
    #pragma unroll
    for (int q = 0; q < 2; q++) {
        #pragma unroll
        for (int it = 0; it < 8; it++) {
            int lin = tid + it * 256;
            int r = lin >> 4, c = lin & 15;
            uint32_t so = SWZ(r, c);
            cp_async16(sb + Aoff[q] + so, (const char*)(g_X16 + (ii[q] * BM + r) * DDIM) + c * 16);
            cp_async16(sb + Boff[q] + so, (const char*)(g_X16 + (jj[q] * BM + r) * DDIM) + c * 16);
        }
        if (tid < 64) {
            cp_async16(sb + MAoff[q] + tid * 16, (const char*)(g_meta + ii[q] * BM) + tid * 16);
            cp_async16(sb + MBoff[q] + tid * 16, (const char*)(g_meta + jj[q] * BM) + tid * 16);
        }
        CP_COMMIT();
    }

    // ldmatrix relative offsets (swizzle XOR term is lane&7 for every fragment)
    const int hi = lane >> 4, sw = lane & 7, rl = lane & 15;
    uint32_t aRel[2], bRel[4];
    #pragma unroll
    for (int mf = 0; mf < 2; mf++) aRel[mf] = (uint32_t)(warpM * 32 + mf * 16 + rl) * 256;
    #pragma unroll
    for (int bn = 0; bn < 4; bn++) bRel[bn] = (uint32_t)(warpN * 64 + bn * 16 + rl) * 256;

    unsigned* smine = reinterpret_cast<unsigned*>(smem + SM_MINE);

    for (int q = 0; q < 2; q++) {
        // init mining smem: [0:128) rowHP=0, [128:256) rowHN=inf, [256:384) colHP=0, [384:512) colHN=inf
        {
            unsigned iv = (tid & 128) ? 0x7f800000u : 0u;
            smine[tid] = iv;
            smine[tid + 256] = iv;
        }
        if (q == 0) CP_WAIT(1); else CP_WAIT(0);
        __syncthreads();

        const float2* mA = reinterpret_cast<const float2*>(smem + MAoff[q]);
        const float2* mB = reinterpret_cast<const float2*>(smem + MBoff[q]);

        float sqa[4]; int labA[4];
        #pragma unroll
        for (int mf = 0; mf < 2; mf++) {
            float2 m0 = mA[warpM * 32 + mf * 16 + (lane >> 2)];
            float2 m1 = mA[warpM * 32 + mf * 16 + 8 + (lane >> 2)];
            sqa[mf * 2]     = m0.y; labA[mf * 2]     = __float_as_int(m0.x);
            sqa[mf * 2 + 1] = m1.y; labA[mf * 2 + 1] = __float_as_int(m1.x);
        }

        // ---- GEMM 128x128x128 ----
        float acc[2][8][4];
        #pragma unroll
        for (int mf = 0; mf < 2; mf++)
            #pragma unroll
            for (int nf = 0; nf < 8; nf++)
                #pragma unroll
                for (int e = 0; e < 4; e++) acc[mf][nf][e] = 0.f;

        #pragma unroll
        for (int kc = 0; kc < 8; kc++) {
            const uint32_t cx = (uint32_t)(((2 * kc + hi) ^ sw) * 16);
            uint32_t a[2][4], b[4][4];
            #pragma unroll
            for (int mf = 0; mf < 2; mf++) ldsm_x4(a[mf], sb + Aoff[q] + aRel[mf] + cx);
            #pragma unroll
            for (int bn = 0; bn < 4; bn++) ldsm_x4(b[bn], sb + Boff[q] + bRel[bn] + cx);
            #pragma unroll
            for (int mf = 0; mf < 2; mf++) {
                #pragma unroll
                for (int bn = 0; bn < 4; bn++) {
                    mma16816(acc[mf][bn * 2],     a[mf], b[bn][0], b[bn][2]);
                    mma16816(acc[mf][bn * 2 + 1], a[mf], b[bn][1], b[bn][3]);
                }
            }
        }

        // ---- epilogue: dual-direction mining ----
        float hp[4], hn[4], hpc[16], hnc[16];
        #pragma unroll
        for (int e = 0; e < 4; e++) { hp[e] = 0.f; hn[e] = __int_as_float(0x7f800000); }
        #pragma unroll
        for (int e = 0; e < 16; e++) { hpc[e] = 0.f; hnc[e] = __int_as_float(0x7f800000); }

        #pragma unroll
        for (int nf = 0; nf < 8; nf++) {
            const int cb = warpN * 64 + nf * 8 + (lane & 3) * 2;
            const float2 mv0 = mB[cb], mv1 = mB[cb + 1];
            const int lb0 = __float_as_int(mv0.x), lb1 = __float_as_int(mv1.x);
            #pragma unroll
            for (int mf = 0; mf < 2; mf++) {
                const int rlo = mf * 2, rhi = mf * 2 + 1;
                float d00 = fmaxf(fmaf(-2.f, acc[mf][nf][0], sqa[rlo] + mv0.y), 0.f);
                float d01 = fmaxf(fmaf(-2.f, acc[mf][nf][1], sqa[rlo] + mv1.y), 0.f);
                float d10 = fmaxf(fmaf(-2.f, acc[mf][nf][2], sqa[rhi] + mv0.y), 0.f);
                float d11 = fmaxf(fmaf(-2.f, acc[mf][nf][3], sqa[rhi] + mv1.y), 0.f);
                if (lb0 == labA[rlo]) { hp[rlo] = fmaxf(hp[rlo], d00); hpc[nf*2]   = fmaxf(hpc[nf*2],   d00); }
                else                  { hn[rlo] = fminf(hn[rlo], d00); hnc[nf*2]   = fminf(hnc[nf*2],   d00); }
                if (lb1 == labA[rlo]) { hp[rlo] = fmaxf(hp[rlo], d01); hpc[nf*2+1] = fmaxf(hpc[nf*2+1], d01); }
                else                  { hn[rlo] = fminf(hn[rlo], d01); hnc[nf*2+1] = fminf(hnc[nf*2+1], d01); }
                if (lb0 == labA[rhi]) { hp[rhi] = fmaxf(hp[rhi], d10); hpc[nf*2]   = fmaxf(hpc[nf*2],   d10); }
                else                  { hn[rhi] = fminf(hn[rhi], d10); hnc[nf*2]   = fminf(hnc[nf*2],   d10); }
                if (lb1 == labA[rhi]) { hp[rhi] = fmaxf(hp[rhi], d11); hpc[nf*2+1] = fmaxf(hpc[nf*2+1], d11); }
                else                  { hn[rhi] = fminf(hn[rhi], d11); hnc[nf*2+1] = fminf(hnc[nf*2+1], d11); }
            }
        }

        // row reduce across lane&3 (cols within warp)
        #pragma unroll
        for (int e = 0; e < 4; e++) {
            hp[e] = fmaxf(hp[e], __shfl_xor_sync(0xffffffffu, hp[e], 1));
            hp[e] = fmaxf(hp[e], __shfl_xor_sync(0xffffffffu, hp[e], 2));
            hn[e] = fminf(hn[e], __shfl_xor_sync(0xffffffffu, hn[e], 1));
            hn[e] = fminf(hn[e], __shfl_xor_sync(0xffffffffu, hn[e], 2));
        }
        // col reduce across lane>>2 (rows within warp)
        #pragma unroll
        for (int e = 0; e < 16; e++) {
            hpc[e] = fmaxf(hpc[e], __shfl_xor_sync(0xffffffffu, hpc[e], 4));
            hpc[e] = fmaxf(hpc[e], __shfl_xor_sync(0xffffffffu, hpc[e], 8));
            hpc[e] = fmaxf(hpc[e], __shfl_xor_sync(0xffffffffu, hpc[e], 16));
            hnc[e] = fminf(hnc[e], __shfl_xor_sync(0xffffffffu, hnc[e], 4));
            hnc[e] = fminf(hnc[e], __shfl_xor_sync(0xffffffffu, hnc[e], 8));
            hnc[e] = fminf(hnc[e], __shfl_xor_sync(0xffffffffu, hnc[e], 16));
        }

        unsigned* rowHP = smine;
        unsigned* rowHN = smine + 128;
        unsigned* colHP = smine + 256;
        unsigned* colHN = smine + 384;

        if ((lane & 3) == 0) {
            #pragma unroll
            for (int e = 0; e < 4; e++) {
                int r = warpM * 32 + (e >> 1) * 16 + (e & 1) * 8 + (lane >> 2);
                atomicMax(&rowHP[r], __float_as_uint(hp[e]));
                atomicMin(&rowHN[r], __float_as_uint(hn[e]));
            }
        }
        {
            const int nf = lane >> 2;
            const int cb = warpN * 64 + nf * 8 + (lane & 3) * 2;
            atomicMax(&colHP[cb],     __float_as_uint(hpc[nf * 2]));
            atomicMin(&colHN[cb],     __float_as_uint(hnc[nf * 2]));
            atomicMax(&colHP[cb + 1], __float_as_uint(hpc[nf * 2 + 1]));
            atomicMin(&colHN[cb + 1], __float_as_uint(hnc[nf * 2 + 1]));
        }
        __syncthreads();
        if (tid < 128) {
            atomicMax(&g_hp[ii[q] * BM + tid], rowHP[tid]);
            atomicMin(&g_hn[ii[q] * BM + tid], rowHN[tid]);
            atomicMax(&g_hp[jj[q] * BM + tid], colHP[tid]);
            atomicMin(&g_hn[jj[q] * BM + tid], colHN[tid]);
        }
        __syncthreads();   // protect smine re-init for the next pair
    }
}

// ---------------- finalize: 64 blocks, deterministic fixed-point accumulation ----------------
__global__ void finalize_kernel(float* __restrict__ out) {
    __shared__ float red[4];
    const int tid = threadIdx.x, wid = tid >> 5, lane = tid & 31;
    const int r = blockIdx.x * 128 + tid;
    float hp = sqrtf(__uint_as_float(g_hp[r]));
    float hn = sqrtf(__uint_as_float(g_hn[r]));
    float s = fmaxf(hp - hn + MARGIN, 0.f);
    #pragma unroll
    for (int o = 16; o; o >>= 1) s += __shfl_xor_sync(0xffffffffu, s, o);
    if (lane == 0) red[wid] = s;
    __syncthreads();
    if (tid == 0) {
        float bs = red[0] + red[1] + red[2] + red[3];
        unsigned long long qv = (unsigned long long)__float2ll_rn(bs * 16777216.0f);
        atomicAdd(&g_isum, qv);
        __threadfence();
        unsigned done = atomicAdd(&g_done, 1u);
        if (done == 63u) {
            unsigned long long v = atomicAdd(&g_isum, 0ull);
            out[0] = (float)((double)v * (1.0 / (16777216.0 * 8192.0)));
        }
    }
}

extern "C" void kernel_launch(void* const* d_in, const int* in_sizes, int n_in,
                              void* d_out, int out_size) {
    const float* X   = (const float*)d_in[0];
    const int* lab32 = (const int*)d_in[1];
    float* out = (float*)d_out;

    cudaFuncSetAttribute(mma_kernel, cudaFuncAttributeMaxDynamicSharedMemorySize, SM_TOT);

    prep_kernel<<<NROWS / 64, 256>>>(X, lab32);
    mma_kernel<<<GRID_MMA, 256, SM_TOT>>>();
    finalize_kernel<<<64, 128>>>(out);
}

// round 9
// speedup vs baseline: 9.2982x; 1.4747x over previous
#include <cuda_runtime.h>
#include <cuda_fp16.h>
#include <cstdint>

#define NROWS  8192
#define DDIM   128
#define BM     128
#define NB     (NROWS / BM)              // 64
#define NPAIRS (NB * (NB + 1) / 2)       // 2080
#define GRID_MMA 296                     // 2 per SM, persistent
#define MARGIN 0.3f

// ---------------- device scratch (no allocations allowed) ----------------
__device__ unsigned g_hp[NROWS];
__device__ unsigned g_hn[NROWS];
__device__ __align__(16) float2 g_meta[NROWS];        // {label bits, sqnorm}
__device__ __align__(16) __half g_X16[NROWS * DDIM];
__device__ unsigned long long g_isum;
__device__ unsigned g_done;
__device__ int g_work;

// ---------------- helpers ----------------
__device__ __forceinline__ uint32_t smem_u32(const void* p) {
    uint32_t a;
    asm("{ .reg .u64 t; cvta.to.shared.u64 t, %1; cvt.u32.u64 %0, t; }" : "=r"(a) : "l"(p));
    return a;
}
__device__ __forceinline__ void cp_async16(uint32_t s, const void* g) {
    asm volatile("cp.async.cg.shared.global [%0], [%1], 16;" :: "r"(s), "l"(g));
}
#define CP_COMMIT() asm volatile("cp.async.commit_group;" ::: "memory")
#define CP_WAIT0()  asm volatile("cp.async.wait_group 0;" ::: "memory")

__device__ __forceinline__ void ldsm_x4(uint32_t* d, uint32_t addr) {
    asm volatile("ldmatrix.sync.aligned.m8n8.x4.shared.b16 {%0,%1,%2,%3}, [%4];"
                 : "=r"(d[0]), "=r"(d[1]), "=r"(d[2]), "=r"(d[3]) : "r"(addr));
}
__device__ __forceinline__ void mma16816(float* c, const uint32_t* a, uint32_t b0, uint32_t b1) {
    asm volatile("mma.sync.aligned.m16n8k16.row.col.f32.f16.f16.f32 "
                 "{%0,%1,%2,%3}, {%4,%5,%6,%7}, {%8,%9}, {%0,%1,%2,%3};"
                 : "+f"(c[0]), "+f"(c[1]), "+f"(c[2]), "+f"(c[3])
                 : "r"(a[0]), "r"(a[1]), "r"(a[2]), "r"(a[3]), "r"(b0), "r"(b1));
}

// swizzled byte offset within a 128x128 fp16 tile: row r (256B rows), 16B chunk c16
#define SWZ(r, c) ((uint32_t)((r) * 256 + ((((c) ^ ((r) & 7))) * 16)))

// ---------------- smem layout (bytes): single pair buffer, fits 2 CTA/SM ----------------
#define SM_A    0
#define SM_B    32768
#define SM_MA   65536
#define SM_MB   66560
#define SM_MINE 67584           // 512 u32: rowHP rowHN colHP colHN
#define SM_TOT  69664           // +32 for the work-index slot

// ---------------- prep: one row per warp; cheap label-width detect ----------------
__global__ __launch_bounds__(256) void prep_kernel(const float* __restrict__ X,
                                                   const int* __restrict__ lab32) {
    __shared__ int smode;
    const int tid = threadIdx.x, wid = tid >> 5, lane = tid & 31;
    if (tid == 0) {
        smode = 1;
        if (blockIdx.x == 0) { g_isum = 0ull; g_done = 0u; g_work = 0; }
    }
    __syncthreads();
    // int64 labels (values<2^31) => odd 32-bit words all zero. 64 samples: P(false+) ~ 256^-64.
    if (tid < 64 && lab32[2 * tid + 1] != 0) smode = 0;   // benign race: only writes 0
    __syncthreads();
    const int m64 = smode;

    const int row = blockIdx.x * 8 + wid;
    float4 v = reinterpret_cast<const float4*>(X + row * DDIM)[lane];
    float s = v.x * v.x;
    s = fmaf(v.y, v.y, s);
    s = fmaf(v.z, v.z, s);
    s = fmaf(v.w, v.w, s);
    #pragma unroll
    for (int o = 16; o; o >>= 1) s += __shfl_xor_sync(0xffffffffu, s, o);
    __half2 h0 = __floats2half2_rn(v.x, v.y);
    __half2 h1 = __floats2half2_rn(v.z, v.w);
    __half2* dst = reinterpret_cast<__half2*>(g_X16 + row * DDIM) + lane * 2;
    dst[0] = h0;
    dst[1] = h1;
    if (lane == 0) {
        int lab = m64 ? lab32[2 * row] : lab32[row];
        float2 m; m.x = __int_as_float(lab); m.y = s;
        g_meta[row] = m;
        g_hp[row] = 0u;
        g_hn[row] = 0x7f800000u;
    }
}

// ---------------- persistent symmetric HMMA Gram + dual-direction mining ----------------
__global__ __launch_bounds__(256, 2) void mma_kernel() {
    extern __shared__ char smem[];
    const uint32_t sb = smem_u32(smem);
    const int tid = threadIdx.x, wid = tid >> 5, lane = tid & 31;
    const int warpM = wid & 3, warpN = wid >> 2;     // 4 M-warps x 2 N-warps, warp tile 32x64
    int* s_p = reinterpret_cast<int*>(smem + SM_MINE + 2048);

    // ldmatrix relative offsets (swizzle XOR term is lane&7 for every fragment)
    const int hi = lane >> 4, sw = lane & 7, rl = lane & 15;
    uint32_t aRel[2], bRel[4];
    #pragma unroll
    for (int mf = 0; mf < 2; mf++) aRel[mf] = sb + SM_A + (uint32_t)(warpM * 32 + mf * 16 + rl) * 256;
    #pragma unroll
    for (int bn = 0; bn < 4; bn++) bRel[bn] = sb + SM_B + (uint32_t)(warpN * 64 + bn * 16 + rl) * 256;

    unsigned* rowHP = reinterpret_cast<unsigned*>(smem + SM_MINE);
    unsigned* rowHN = rowHP + 128;
    unsigned* colHP = rowHP + 256;
    unsigned* colHN = rowHP + 384;
    const float2* mA = reinterpret_cast<const float2*>(smem + SM_MA);
    const float2* mB = reinterpret_cast<const float2*>(smem + SM_MB);

    for (;;) {
        if (tid == 0) *s_p = atomicAdd(&g_work, 1);
        __syncthreads();                       // also fences prev-iter smine reads
        const int p = *s_p;
        if (p >= NPAIRS) break;

        // decode triangular pair: i s.t. T(i)=i*(129-i)/2 <= p < T(i+1)
        int i = (int)((129.0f - sqrtf(16641.0f - 8.0f * (float)p)) * 0.5f);
        while ((i + 1) * (129 - (i + 1)) / 2 <= p) i++;
        while (i * (129 - i) / 2 > p) i--;
        const int j = i + (p - i * (129 - i) / 2);

        // issue loads for this pair
        #pragma unroll
        for (int it = 0; it < 8; it++) {
            int lin = tid + it * 256;
            int r = lin >> 4, c = lin & 15;
            uint32_t so = SWZ(r, c);
            cp_async16(sb + SM_A + so, (const char*)(g_X16 + (i * BM + r) * DDIM) + c * 16);
            cp_async16(sb + SM_B + so, (const char*)(g_X16 + (j * BM + r) * DDIM) + c * 16);
        }
        if (tid < 64) {
            cp_async16(sb + SM_MA + tid * 16, (const char*)(g_meta + i * BM) + tid * 16);
            cp_async16(sb + SM_MB + tid * 16, (const char*)(g_meta + j * BM) + tid * 16);
        }
        CP_COMMIT();

        // init mining smem while loads fly
        {
            unsigned iv = (tid & 128) ? 0x7f800000u : 0u;
            rowHP[tid] = iv;          // covers rowHP+rowHN
            rowHP[tid + 256] = iv;    // covers colHP+colHN
        }
        CP_WAIT0();
        __syncthreads();

        float sqa[4]; int labA[4];
        #pragma unroll
        for (int mf = 0; mf < 2; mf++) {
            float2 m0 = mA[warpM * 32 + mf * 16 + (lane >> 2)];
            float2 m1 = mA[warpM * 32 + mf * 16 + 8 + (lane >> 2)];
            sqa[mf * 2]     = m0.y; labA[mf * 2]     = __float_as_int(m0.x);
            sqa[mf * 2 + 1] = m1.y; labA[mf * 2 + 1] = __float_as_int(m1.x);
        }

        // ---- GEMM 128x128x128 ----
        float acc[2][8][4];
        #pragma unroll
        for (int mf = 0; mf < 2; mf++)
            #pragma unroll
            for (int nf = 0; nf < 8; nf++)
                #pragma unroll
                for (int e = 0; e < 4; e++) acc[mf][nf][e] = 0.f;

        #pragma unroll
        for (int kc = 0; kc < 8; kc++) {
            const uint32_t cx = (uint32_t)(((2 * kc + hi) ^ sw) * 16);
            uint32_t a[2][4], b[4][4];
            #pragma unroll
            for (int mf = 0; mf < 2; mf++) ldsm_x4(a[mf], aRel[mf] + cx);
            #pragma unroll
            for (int bn = 0; bn < 4; bn++) ldsm_x4(b[bn], bRel[bn] + cx);
            #pragma unroll
            for (int mf = 0; mf < 2; mf++) {
                #pragma unroll
                for (int bn = 0; bn < 4; bn++) {
                    mma16816(acc[mf][bn * 2],     a[mf], b[bn][0], b[bn][2]);
                    mma16816(acc[mf][bn * 2 + 1], a[mf], b[bn][1], b[bn][3]);
                }
            }
        }

        // ---- epilogue: dual mining; col temps reduced per-nf (low reg pressure) ----
        float hp[4], hn[4];
        #pragma unroll
        for (int e = 0; e < 4; e++) { hp[e] = 0.f; hn[e] = __int_as_float(0x7f800000); }

        #pragma unroll
        for (int nf = 0; nf < 8; nf++) {
            const int cb = warpN * 64 + nf * 8 + (lane & 3) * 2;
            const float2 mv0 = mB[cb], mv1 = mB[cb + 1];
            const int lb0 = __float_as_int(mv0.x), lb1 = __float_as_int(mv1.x);
            float cp0 = 0.f, cp1 = 0.f;
            float cn0 = __int_as_float(0x7f800000), cn1 = cn0;
            #pragma unroll
            for (int mf = 0; mf < 2; mf++) {
                const int rlo = mf * 2, rhi = mf * 2 + 1;
                float d00 = fmaxf(fmaf(-2.f, acc[mf][nf][0], sqa[rlo] + mv0.y), 0.f);
                float d01 = fmaxf(fmaf(-2.f, acc[mf][nf][1], sqa[rlo] + mv1.y), 0.f);
                float d10 = fmaxf(fmaf(-2.f, acc[mf][nf][2], sqa[rhi] + mv0.y), 0.f);
                float d11 = fmaxf(fmaf(-2.f, acc[mf][nf][3], sqa[rhi] + mv1.y), 0.f);
                if (lb0 == labA[rlo]) { hp[rlo] = fmaxf(hp[rlo], d00); cp0 = fmaxf(cp0, d00); }
                else                  { hn[rlo] = fminf(hn[rlo], d00); cn0 = fminf(cn0, d00); }
                if (lb1 == labA[rlo]) { hp[rlo] = fmaxf(hp[rlo], d01); cp1 = fmaxf(cp1, d01); }
                else                  { hn[rlo] = fminf(hn[rlo], d01); cn1 = fminf(cn1, d01); }
                if (lb0 == labA[rhi]) { hp[rhi] = fmaxf(hp[rhi], d10); cp0 = fmaxf(cp0, d10); }
                else                  { hn[rhi] = fminf(hn[rhi], d10); cn0 = fminf(cn0, d10); }
                if (lb1 == labA[rhi]) { hp[rhi] = fmaxf(hp[rhi], d11); cp1 = fmaxf(cp1, d11); }
                else                  { hn[rhi] = fminf(hn[rhi], d11); cn1 = fminf(cn1, d11); }
            }
            // reduce col temps across the 8 lanes (lane>>2) sharing these 2 columns
            #pragma unroll
            for (int o = 4; o <= 16; o <<= 1) {
                cp0 = fmaxf(cp0, __shfl_xor_sync(0xffffffffu, cp0, o));
                cp1 = fmaxf(cp1, __shfl_xor_sync(0xffffffffu, cp1, o));
                cn0 = fminf(cn0, __shfl_xor_sync(0xffffffffu, cn0, o));
                cn1 = fminf(cn1, __shfl_xor_sync(0xffffffffu, cn1, o));
            }
            if (lane < 4) {
                const int cc = warpN * 64 + nf * 8 + lane * 2;
                atomicMax(&colHP[cc],     __float_as_uint(cp0));
                atomicMin(&colHN[cc],     __float_as_uint(cn0));
                atomicMax(&colHP[cc + 1], __float_as_uint(cp1));
                atomicMin(&colHN[cc + 1], __float_as_uint(cn1));
            }
        }

        // row reduce across lane&3 (cols within warp)
        #pragma unroll
        for (int e = 0; e < 4; e++) {
            hp[e] = fmaxf(hp[e], __shfl_xor_sync(0xffffffffu, hp[e], 1));
            hp[e] = fmaxf(hp[e], __shfl_xor_sync(0xffffffffu, hp[e], 2));
            hn[e] = fminf(hn[e], __shfl_xor_sync(0xffffffffu, hn[e], 1));
            hn[e] = fminf(hn[e], __shfl_xor_sync(0xffffffffu, hn[e], 2));
        }
        if ((lane & 3) == 0) {
            #pragma unroll
            for (int e = 0; e < 4; e++) {
                int r = warpM * 32 + (e >> 1) * 16 + (e & 1) * 8 + (lane >> 2);
                atomicMax(&rowHP[r], __float_as_uint(hp[e]));
                atomicMin(&rowHN[r], __float_as_uint(hn[e]));
            }
        }
        __syncthreads();
        if (tid < 128) {
            atomicMax(&g_hp[i * BM + tid], rowHP[tid]);
            atomicMin(&g_hn[i * BM + tid], rowHN[tid]);
            atomicMax(&g_hp[j * BM + tid], colHP[tid]);
            atomicMin(&g_hn[j * BM + tid], colHN[tid]);
        }
    }
}

// ---------------- finalize: 64 blocks, deterministic fixed-point accumulation ----------------
__global__ void finalize_kernel(float* __restrict__ out) {
    __shared__ float red[4];
    const int tid = threadIdx.x, wid = tid >> 5, lane = tid & 31;
    const int r = blockIdx.x * 128 + tid;
    float hp = sqrtf(__uint_as_float(g_hp[r]));
    float hn = sqrtf(__uint_as_float(g_hn[r]));
    float s = fmaxf(hp - hn + MARGIN, 0.f);
    #pragma unroll
    for (int o = 16; o; o >>= 1) s += __shfl_xor_sync(0xffffffffu, s, o);
    if (lane == 0) red[wid] = s;
    __syncthreads();
    if (tid == 0) {
        float bs = red[0] + red[1] + red[2] + red[3];
        unsigned long long qv = (unsigned long long)__float2ll_rn(bs * 16777216.0f);
        atomicAdd(&g_isum, qv);
        __threadfence();
        unsigned done = atomicAdd(&g_done, 1u);
        if (done == 63u) {
            unsigned long long v = atomicAdd(&g_isum, 0ull);
            out[0] = (float)((double)v * (1.0 / (16777216.0 * 8192.0)));
        }
    }
}

extern "C" void kernel_launch(void* const* d_in, const int* in_sizes, int n_in,
                              void* d_out, int out_size) {
    const float* X   = (const float*)d_in[0];
    const int* lab32 = (const int*)d_in[1];
    float* out = (float*)d_out;

    cudaFuncSetAttribute(mma_kernel, cudaFuncAttributeMaxDynamicSharedMemorySize, SM_TOT);

    prep_kernel<<<NROWS / 8, 256>>>(X, lab32);
    mma_kernel<<<GRID_MMA, 256, SM_TOT>>>();
    finalize_kernel<<<64, 128>>>(out);
}